// round 13
// baseline (speedup 1.0000x reference)
#include <cuda_runtime.h>
#include <cuda_fp16.h>
#include <math.h>
#include <stdint.h>

#define BATCH 2
#define SEQ   2048
#define DMODEL 512
#define NHEAD 8
#define HDIM  64
#define MROWS (BATCH * SEQ)   // 4096

typedef __half f16;
typedef __half2 f162;

// ---------------------------------------------------------------------------
// Device-global scratch
// ---------------------------------------------------------------------------
__device__ f16 g_xh[MROWS * DMODEL];
__device__ f16 g_xl[MROWS * DMODEL];
__device__ f16 g_w1[3 * DMODEL * DMODEL];     // w_qkv^T fp16 (single)
__device__ f16 g_w2[DMODEL * DMODEL];         // w_out^T fp16 (single)
__device__ f16 g_qkvh[MROWS * 3 * DMODEL];
__device__ f16 g_qkvl[MROWS * 3 * DMODEL];
__device__ f16 g_ah[MROWS * DMODEL];
__device__ f16 g_al[MROWS * DMODEL];

__device__ __forceinline__ uint32_t smem_u32(const void* p) {
    return (uint32_t)__cvta_generic_to_shared(p);
}
__device__ __forceinline__ uint32_t pack2h(float a, float b) {
    f162 t;
    t.x = __float2half_rn(a);
    t.y = __float2half_rn(b);
    return *(uint32_t*)&t;
}

#define MMA_F16(c, a, b)                                                       \
    asm volatile(                                                              \
        "mma.sync.aligned.m16n8k16.row.col.f32.f16.f16.f32 "                   \
        "{%0,%1,%2,%3},{%4,%5,%6,%7},{%8,%9},{%0,%1,%2,%3};"                   \
        : "+f"((c)[0]), "+f"((c)[1]), "+f"((c)[2]), "+f"((c)[3])               \
        : "r"((a)[0]), "r"((a)[1]), "r"((a)[2]), "r"((a)[3]),                  \
          "r"((b)[0]), "r"((b)[1]))

#define LDSM_X4(r, addr)                                                       \
    asm volatile("ldmatrix.sync.aligned.m8n8.x4.shared.b16 {%0,%1,%2,%3}, [%4];" \
                 : "=r"((r)[0]), "=r"((r)[1]), "=r"((r)[2]), "=r"((r)[3])      \
                 : "r"(addr))

#define LDSM_X2(r, addr)                                                       \
    asm volatile("ldmatrix.sync.aligned.m8n8.x2.shared.b16 {%0,%1}, [%2];"     \
                 : "=r"((r)[0]), "=r"((r)[1]) : "r"(addr))

#define LDSM_X2T(r, addr)                                                      \
    asm volatile("ldmatrix.sync.aligned.m8n8.x2.trans.shared.b16 {%0,%1}, [%2];" \
                 : "=r"((r)[0]), "=r"((r)[1]) : "r"(addr))

#define CP_ASYNC16(dst, src)                                                   \
    asm volatile("cp.async.cg.shared.global [%0], [%1], 16;" ::"r"(dst), "l"(src))

// ---------------------------------------------------------------------------
// fp32 -> fp16 hi/lo split (elementwise)
// ---------------------------------------------------------------------------
__global__ void conv_split_kernel(const float* __restrict__ in,
                                  f16* __restrict__ h, f16* __restrict__ l,
                                  int n4)
{
    int i = blockIdx.x * blockDim.x + threadIdx.x;
    if (i < n4) {
        float4 v = ((const float4*)in)[i];
        f16 h0 = __float2half_rn(v.x), h1 = __float2half_rn(v.y);
        f16 h2 = __float2half_rn(v.z), h3 = __float2half_rn(v.w);
        f162 hh0 = {h0, h1}, hh1 = {h2, h3};
        ((f162*)h)[i * 2 + 0] = hh0;
        ((f162*)h)[i * 2 + 1] = hh1;
        f162 ll0 = {__float2half_rn(v.x - __half2float(h0)),
                    __float2half_rn(v.y - __half2float(h1))};
        f162 ll1 = {__float2half_rn(v.z - __half2float(h2)),
                    __float2half_rn(v.w - __half2float(h3))};
        ((f162*)l)[i * 2 + 0] = ll0;
        ((f162*)l)[i * 2 + 1] = ll1;
    }
}

// Transpose: fp32 [K][N] -> fp16 [N][K] (single precision level)
__global__ void convT_kernel(const float* __restrict__ in,
                             f16* __restrict__ h, int K, int N)
{
    __shared__ float t[32][33];
    int k0 = blockIdx.y * 32, n0 = blockIdx.x * 32;
    int tx = threadIdx.x, ty = threadIdx.y;
    #pragma unroll
    for (int i = 0; i < 4; ++i)
        t[ty + i * 8][tx] = in[(size_t)(k0 + ty + i * 8) * N + n0 + tx];
    __syncthreads();
    #pragma unroll
    for (int i = 0; i < 4; ++i) {
        float v = t[tx][ty + i * 8];
        int n = n0 + ty + i * 8;
        int k = k0 + tx;
        h[(size_t)n * K + k] = __float2half_rn(v);
    }
}

// ---------------------------------------------------------------------------
// Tensor-core GEMM (mma.sync fp16, fp32 acc), activation 2-term split:
// C = Ah*B + Al*B. Tile 128x128x32, 256 threads, smem stride 40,
// cp.async double-buffer. OUTF16=1: emit fp16 hi/lo; else fp32.
// ---------------------------------------------------------------------------
#define GS 40
#define STG_ELEMS (3 * 128 * GS)   // elems per stage (Ah,Al,B)

template <int OUTF16>
__global__ __launch_bounds__(256, 2) void gemm_tc(
    const f16* __restrict__ Ah, const f16* __restrict__ Al,
    const f16* __restrict__ B,
    const float* __restrict__ bias,
    float* __restrict__ Cf, f16* __restrict__ Ch, f16* __restrict__ Cl,
    int M, int N, int K)
{
    extern __shared__ f16 sm[];

    const int tid = threadIdx.x;
    const int warp = tid >> 5, lane = tid & 31;
    const int bm = blockIdx.y * 128, bn = blockIdx.x * 128;
    const int wm = (warp >> 2) * 64, wn = (warp & 3) * 32;
    const int lrow = tid >> 1, lcol = (tid & 1) * 16;

    const f16* gsrc[3];
    gsrc[0] = Ah + (size_t)(bm + lrow) * K + lcol;
    gsrc[1] = Al + (size_t)(bm + lrow) * K + lcol;
    gsrc[2] = B + (size_t)(bn + lrow) * K + lcol;

    uint32_t sdst0[3];
    #pragma unroll
    for (int q = 0; q < 3; ++q)
        sdst0[q] = smem_u32(sm + q * 128 * GS + lrow * GS + lcol);

    float acc[4][4][4];
    #pragma unroll
    for (int i = 0; i < 4; ++i)
        #pragma unroll
        for (int j = 0; j < 4; ++j)
            #pragma unroll
            for (int r = 0; r < 4; ++r) acc[i][j][r] = 0.0f;

    const int nk = K >> 5;

    #pragma unroll
    for (int q = 0; q < 3; ++q) {
        CP_ASYNC16(sdst0[q], gsrc[q]);
        CP_ASYNC16(sdst0[q] + 16, gsrc[q] + 8);
    }
    asm volatile("cp.async.commit_group;");
    asm volatile("cp.async.wait_group 0;");
    __syncthreads();

    for (int t = 0; t < nk; ++t) {
        if (t + 1 < nk) {
            uint32_t so = ((t + 1) & 1) * (STG_ELEMS * 2);
            int off = (t + 1) * 32;
            #pragma unroll
            for (int q = 0; q < 3; ++q) {
                CP_ASYNC16(sdst0[q] + so, gsrc[q] + off);
                CP_ASYNC16(sdst0[q] + so + 16, gsrc[q] + off + 8);
            }
            asm volatile("cp.async.commit_group;");
        }

        const f16* base = sm + (t & 1) * STG_ELEMS;
        const f16* sAh = base;
        const f16* sAl = base + 128 * GS;
        const f16* sB  = base + 2 * 128 * GS;

        #pragma unroll
        for (int ks = 0; ks < 32; ks += 16) {
            uint32_t bh[4][2];
            #pragma unroll
            for (int nt = 0; nt < 4; ++nt) {
                uint32_t ab = smem_u32(&sB[(wn + nt * 8 + (lane & 7)) * GS +
                                           ks + ((lane >> 3) & 1) * 8]);
                LDSM_X2(bh[nt], ab);
            }
            #pragma unroll
            for (int mtp = 0; mtp < 4; mtp += 2) {
                uint32_t afh0[4], afl0[4], afh1[4], afl1[4];
                uint32_t a0 = smem_u32(&sAh[(wm + mtp * 16 + (lane & 15)) * GS +
                                            ks + (lane >> 4) * 8]);
                LDSM_X4(afh0, a0);
                uint32_t a1 = smem_u32(&sAl[(wm + mtp * 16 + (lane & 15)) * GS +
                                            ks + (lane >> 4) * 8]);
                LDSM_X4(afl0, a1);
                uint32_t a2 = smem_u32(&sAh[(wm + (mtp + 1) * 16 + (lane & 15)) * GS +
                                            ks + (lane >> 4) * 8]);
                LDSM_X4(afh1, a2);
                uint32_t a3 = smem_u32(&sAl[(wm + (mtp + 1) * 16 + (lane & 15)) * GS +
                                            ks + (lane >> 4) * 8]);
                LDSM_X4(afl1, a3);
                // pass h: 8 independent MMAs
                #pragma unroll
                for (int nt = 0; nt < 4; ++nt)
                    MMA_F16(acc[mtp][nt], afh0, bh[nt]);
                #pragma unroll
                for (int nt = 0; nt < 4; ++nt)
                    MMA_F16(acc[mtp + 1][nt], afh1, bh[nt]);
                // pass l
                #pragma unroll
                for (int nt = 0; nt < 4; ++nt)
                    MMA_F16(acc[mtp][nt], afl0, bh[nt]);
                #pragma unroll
                for (int nt = 0; nt < 4; ++nt)
                    MMA_F16(acc[mtp + 1][nt], afl1, bh[nt]);
            }
        }
        asm volatile("cp.async.wait_group 0;");
        __syncthreads();
    }

    #pragma unroll
    for (int mt = 0; mt < 4; ++mt) {
        #pragma unroll
        for (int nt = 0; nt < 4; ++nt) {
            int row = bm + wm + mt * 16 + (lane >> 2);
            int col = bn + wn + nt * 8 + (lane & 3) * 2;
            float bx = bias[col], by = bias[col + 1];
            float v0 = acc[mt][nt][0] + bx, v1 = acc[mt][nt][1] + by;
            float v2 = acc[mt][nt][2] + bx, v3 = acc[mt][nt][3] + by;
            if (OUTF16) {
                uint32_t hh0 = pack2h(v0, v1);
                f162 th0 = *(f162*)&hh0;
                *(uint32_t*)(Ch + (size_t)row * N + col) = hh0;
                *(uint32_t*)(Cl + (size_t)row * N + col) =
                    pack2h(v0 - __half2float(th0.x), v1 - __half2float(th0.y));
                uint32_t hh1 = pack2h(v2, v3);
                f162 th1 = *(f162*)&hh1;
                *(uint32_t*)(Ch + (size_t)(row + 8) * N + col) = hh1;
                *(uint32_t*)(Cl + (size_t)(row + 8) * N + col) =
                    pack2h(v2 - __half2float(th1.x), v3 - __half2float(th1.y));
            } else {
                float2 f0 = {v0, v1}, f1 = {v2, v3};
                *(float2*)(Cf + (size_t)row * N + col) = f0;
                *(float2*)(Cf + (size_t)(row + 8) * N + col) = f1;
            }
        }
    }
}

// ---------------------------------------------------------------------------
// Tensor-core sliding-window attention (mma.sync fp16, 3-product split).
// V row-major; P*V uses ldmatrix.x2.trans for B fragments.
// ---------------------------------------------------------------------------
#define A_KH 0
#define A_KL (128 * 72)
#define A_VH (2 * 128 * 72)
#define A_VL (3 * 128 * 72)
#define A_QH (4 * 128 * 72)
#define A_QL (4 * 128 * 72 + 64 * 72)
#define A_SMEM_ELEMS (4 * 128 * 72 + 2 * 64 * 72)   // 46080 elems = 92160 B

__global__ __launch_bounds__(128) void attn_tc_kernel(
    const f16* __restrict__ qkvh, const f16* __restrict__ qkvl,
    f16* __restrict__ outh, f16* __restrict__ outl)
{
    extern __shared__ f16 sm[];

    const int tid = threadIdx.x;
    const int warp = tid >> 5, lane = tid & 31;
    const int s0 = blockIdx.x * 64;
    const int h = blockIdx.y;
    const int b = blockIdx.z;

    {
        int pos = s0 - 32 + tid;
        uint4* dkh = (uint4*)(sm + A_KH + tid * 72);
        uint4* dkl = (uint4*)(sm + A_KL + tid * 72);
        uint4* dvh = (uint4*)(sm + A_VH + tid * 72);
        uint4* dvl = (uint4*)(sm + A_VL + tid * 72);
        if (pos >= 0 && pos < SEQ) {
            size_t rowb = (size_t)(b * SEQ + pos) * (3 * DMODEL);
            const uint4* kh = (const uint4*)(qkvh + rowb + DMODEL + h * HDIM);
            const uint4* kl = (const uint4*)(qkvl + rowb + DMODEL + h * HDIM);
            const uint4* vh = (const uint4*)(qkvh + rowb + 2 * DMODEL + h * HDIM);
            const uint4* vl = (const uint4*)(qkvl + rowb + 2 * DMODEL + h * HDIM);
            #pragma unroll
            for (int i = 0; i < 8; ++i) {
                dkh[i] = kh[i]; dkl[i] = kl[i];
                dvh[i] = vh[i]; dvl[i] = vl[i];
            }
        } else {
            uint4 z = {0, 0, 0, 0};
            #pragma unroll
            for (int i = 0; i < 8; ++i) {
                dkh[i] = z; dkl[i] = z; dvh[i] = z; dvl[i] = z;
            }
        }
        int qr = tid >> 1, qo = (tid & 1) * 32;
        size_t rq = (size_t)(b * SEQ + s0 + qr) * (3 * DMODEL) + h * HDIM + qo;
        const uint4* qh = (const uint4*)(qkvh + rq);
        const uint4* ql = (const uint4*)(qkvl + rq);
        uint4* dqh = (uint4*)(sm + A_QH + qr * 72 + qo);
        uint4* dql = (uint4*)(sm + A_QL + qr * 72 + qo);
        #pragma unroll
        for (int i = 0; i < 4; ++i) { dqh[i] = qh[i]; dql[i] = ql[i]; }
    }
    __syncthreads();

    // ---- S = Q K^T ----
    float s[16][4];
    #pragma unroll
    for (int nt = 0; nt < 16; ++nt)
        #pragma unroll
        for (int j = 0; j < 4; ++j) s[nt][j] = 0.0f;

    const int qrow = warp * 16 + (lane & 15);
    #pragma unroll
    for (int kk = 0; kk < 4; ++kk) {
        uint32_t ah[4], al[4];
        uint32_t aa = smem_u32(sm + A_QH + qrow * 72 + kk * 16 + (lane >> 4) * 8);
        LDSM_X4(ah, aa);
        uint32_t aa2 = smem_u32(sm + A_QL + qrow * 72 + kk * 16 + (lane >> 4) * 8);
        LDSM_X4(al, aa2);
        #pragma unroll
        for (int nt = 0; nt < 16; ++nt) {
            uint32_t bh[2], bl[2];
            uint32_t ba = smem_u32(sm + A_KH + (nt * 8 + (lane & 7)) * 72 +
                                   kk * 16 + ((lane >> 3) & 1) * 8);
            LDSM_X2(bh, ba);
            uint32_t ba2 = smem_u32(sm + A_KL + (nt * 8 + (lane & 7)) * 72 +
                                    kk * 16 + ((lane >> 3) & 1) * 8);
            LDSM_X2(bl, ba2);
            MMA_F16(s[nt], ah, bh);
            MMA_F16(s[nt], ah, bl);
            MMA_F16(s[nt], al, bh);
        }
    }

    // ---- scale + mask + softmax ----
    const int m0 = warp * 16 + (lane >> 2);
    const int m1 = m0 + 8;
    float mx0 = -1e30f, mx1 = -1e30f;
    #pragma unroll
    for (int nt = 0; nt < 16; ++nt) {
        #pragma unroll
        for (int jj = 0; jj < 2; ++jj) {
            int nn = nt * 8 + (lane & 3) * 2 + jj;
            int gpos = s0 - 32 + nn;
            bool vp = (gpos >= 0) && (gpos < SEQ);
            int d0 = nn - m0;
            s[nt][jj] = (vp && d0 >= 0 && d0 <= 64) ? s[nt][jj] * 0.125f : -1e9f;
            int d1 = nn - m1;
            s[nt][2 + jj] = (vp && d1 >= 0 && d1 <= 64) ? s[nt][2 + jj] * 0.125f : -1e9f;
        }
        mx0 = fmaxf(mx0, fmaxf(s[nt][0], s[nt][1]));
        mx1 = fmaxf(mx1, fmaxf(s[nt][2], s[nt][3]));
    }
    mx0 = fmaxf(mx0, __shfl_xor_sync(0xffffffffu, mx0, 1));
    mx0 = fmaxf(mx0, __shfl_xor_sync(0xffffffffu, mx0, 2));
    mx1 = fmaxf(mx1, __shfl_xor_sync(0xffffffffu, mx1, 1));
    mx1 = fmaxf(mx1, __shfl_xor_sync(0xffffffffu, mx1, 2));

    float sum0 = 0.f, sum1 = 0.f;
    #pragma unroll
    for (int nt = 0; nt < 16; ++nt) {
        s[nt][0] = __expf(s[nt][0] - mx0); sum0 += s[nt][0];
        s[nt][1] = __expf(s[nt][1] - mx0); sum0 += s[nt][1];
        s[nt][2] = __expf(s[nt][2] - mx1); sum1 += s[nt][2];
        s[nt][3] = __expf(s[nt][3] - mx1); sum1 += s[nt][3];
    }
    sum0 += __shfl_xor_sync(0xffffffffu, sum0, 1);
    sum0 += __shfl_xor_sync(0xffffffffu, sum0, 2);
    sum1 += __shfl_xor_sync(0xffffffffu, sum1, 1);
    sum1 += __shfl_xor_sync(0xffffffffu, sum1, 2);
    float inv0 = 1.0f / sum0, inv1 = 1.0f / sum1;

    // ---- O = P V ----
    float o[8][4];
    #pragma unroll
    for (int nt = 0; nt < 8; ++nt)
        #pragma unroll
        for (int j = 0; j < 4; ++j) o[nt][j] = 0.0f;

    #pragma unroll
    for (int kt = 0; kt < 8; ++kt) {
        float* pa = s[2 * kt];
        float* pb = s[2 * kt + 1];
        uint32_t ah[4], al[4];
        ah[0] = pack2h(pa[0], pa[1]);
        ah[1] = pack2h(pa[2], pa[3]);
        ah[2] = pack2h(pb[0], pb[1]);
        ah[3] = pack2h(pb[2], pb[3]);
        {
            f162 t0 = *(f162*)&ah[0], t1 = *(f162*)&ah[1];
            f162 t2 = *(f162*)&ah[2], t3 = *(f162*)&ah[3];
            al[0] = pack2h(pa[0] - __half2float(t0.x), pa[1] - __half2float(t0.y));
            al[1] = pack2h(pa[2] - __half2float(t1.x), pa[3] - __half2float(t1.y));
            al[2] = pack2h(pb[0] - __half2float(t2.x), pb[1] - __half2float(t2.y));
            al[3] = pack2h(pb[2] - __half2float(t3.x), pb[3] - __half2float(t3.y));
        }
        uint32_t vrow = (uint32_t)(kt * 16 + (lane & 15)) * 72;
        #pragma unroll
        for (int nt2 = 0; nt2 < 8; ++nt2) {
            uint32_t bh[2], bl[2];
            uint32_t ba = smem_u32(sm + A_VH + vrow + nt2 * 8);
            LDSM_X2T(bh, ba);
            uint32_t ba2 = smem_u32(sm + A_VL + vrow + nt2 * 8);
            LDSM_X2T(bl, ba2);
            MMA_F16(o[nt2], ah, bh);
            MMA_F16(o[nt2], ah, bl);
            MMA_F16(o[nt2], al, bh);
        }
    }

    // ---- normalize + emit fp16 hi/lo ----
    size_t r0 = (size_t)(b * SEQ + s0 + m0) * DMODEL + h * HDIM;
    size_t r1 = r0 + (size_t)8 * DMODEL;
    #pragma unroll
    for (int nt2 = 0; nt2 < 8; ++nt2) {
        int d = nt2 * 8 + (lane & 3) * 2;
        float v0 = o[nt2][0] * inv0, v1 = o[nt2][1] * inv0;
        float v2 = o[nt2][2] * inv1, v3 = o[nt2][3] * inv1;
        uint32_t hh0 = pack2h(v0, v1);
        f162 th0 = *(f162*)&hh0;
        *(uint32_t*)(outh + r0 + d) = hh0;
        *(uint32_t*)(outl + r0 + d) =
            pack2h(v0 - __half2float(th0.x), v1 - __half2float(th0.y));
        uint32_t hh1 = pack2h(v2, v3);
        f162 th1 = *(f162*)&hh1;
        *(uint32_t*)(outh + r1 + d) = hh1;
        *(uint32_t*)(outl + r1 + d) =
            pack2h(v2 - __half2float(th1.x), v3 - __half2float(th1.y));
    }
}

// ---------------------------------------------------------------------------
// Launch
// ---------------------------------------------------------------------------
extern "C" void kernel_launch(void* const* d_in, const int* in_sizes, int n_in,
                              void* d_out, int out_size)
{
    const float* x     = (const float*)d_in[0];
    const float* w_qkv = (const float*)d_in[1];
    const float* b_qkv = (const float*)d_in[2];
    const float* w_out = (const float*)d_in[3];
    const float* b_out = (const float*)d_in[4];
    float* out         = (float*)d_out;

    f16 *xh, *xl, *w1, *w2, *qh, *ql, *ah, *al;
    cudaGetSymbolAddress((void**)&xh, g_xh);
    cudaGetSymbolAddress((void**)&xl, g_xl);
    cudaGetSymbolAddress((void**)&w1, g_w1);
    cudaGetSymbolAddress((void**)&w2, g_w2);
    cudaGetSymbolAddress((void**)&qh, g_qkvh);
    cudaGetSymbolAddress((void**)&ql, g_qkvl);
    cudaGetSymbolAddress((void**)&ah, g_ah);
    cudaGetSymbolAddress((void**)&al, g_al);

    const int M = MROWS;

    {
        int n4 = (M * DMODEL) / 4;
        conv_split_kernel<<<(n4 + 255) / 256, 256>>>(x, xh, xl, n4);
    }
    {
        dim3 blk(32, 8);
        convT_kernel<<<dim3((3 * DMODEL) / 32, DMODEL / 32), blk>>>(
            w_qkv, w1, DMODEL, 3 * DMODEL);
        convT_kernel<<<dim3(DMODEL / 32, DMODEL / 32), blk>>>(
            w_out, w2, DMODEL, DMODEL);
    }

    const int gemm_smem = 2 * STG_ELEMS * (int)sizeof(f16);   // 61440
    cudaFuncSetAttribute(gemm_tc<1>, cudaFuncAttributeMaxDynamicSharedMemorySize, gemm_smem);
    cudaFuncSetAttribute(gemm_tc<0>, cudaFuncAttributeMaxDynamicSharedMemorySize, gemm_smem);

    // GEMM1: qkv (fp16 hi/lo) = x @ w_qkv + b_qkv
    {
        dim3 grid((3 * DMODEL) / 128, M / 128);
        gemm_tc<1><<<grid, 256, gemm_smem>>>(xh, xl, w1, b_qkv,
                                             nullptr, qh, ql, M, 3 * DMODEL, DMODEL);
    }

    // attention (mma.sync fp16)
    {
        int smem = A_SMEM_ELEMS * (int)sizeof(f16);   // 92160
        cudaFuncSetAttribute(attn_tc_kernel,
                             cudaFuncAttributeMaxDynamicSharedMemorySize, smem);
        dim3 grid(SEQ / 64, NHEAD, BATCH);
        attn_tc_kernel<<<grid, 128, smem>>>(qh, ql, ah, al);
    }

    // GEMM2: out (fp32) = attn @ w_out + b_out
    {
        dim3 grid(DMODEL / 128, M / 128);
        gemm_tc<0><<<grid, 256, gemm_smem>>>(ah, al, w2, b_out,
                                             out, nullptr, nullptr, M, DMODEL, DMODEL);
    }
}

// round 15
// speedup vs baseline: 1.5128x; 1.5128x over previous
#include <cuda_runtime.h>
#include <cuda_fp16.h>
#include <math.h>
#include <stdint.h>

#define BATCH 2
#define SEQ   2048
#define DMODEL 512
#define NHEAD 8
#define HDIM  64
#define MROWS (BATCH * SEQ)   // 4096

typedef __half f16;
typedef __half2 f162;

// ---------------------------------------------------------------------------
// Device-global scratch
// ---------------------------------------------------------------------------
__device__ f16 g_xh[MROWS * DMODEL];
__device__ f16 g_xl[MROWS * DMODEL];
__device__ f16 g_w1[3 * DMODEL * DMODEL];     // w_qkv^T fp16
__device__ f16 g_w2[DMODEL * DMODEL];         // w_out^T fp16
__device__ f16 g_qkvh[MROWS * 3 * DMODEL];
__device__ f16 g_qkvl[MROWS * 3 * DMODEL];
__device__ f16 g_ah[MROWS * DMODEL];
__device__ f16 g_al[MROWS * DMODEL];

__device__ __forceinline__ uint32_t smem_u32(const void* p) {
    return (uint32_t)__cvta_generic_to_shared(p);
}
__device__ __forceinline__ uint32_t pack2h(float a, float b) {
    f162 t;
    t.x = __float2half_rn(a);
    t.y = __float2half_rn(b);
    return *(uint32_t*)&t;
}

#define MMA_F16(c, a, b)                                                       \
    asm volatile(                                                              \
        "mma.sync.aligned.m16n8k16.row.col.f32.f16.f16.f32 "                   \
        "{%0,%1,%2,%3},{%4,%5,%6,%7},{%8,%9},{%0,%1,%2,%3};"                   \
        : "+f"((c)[0]), "+f"((c)[1]), "+f"((c)[2]), "+f"((c)[3])               \
        : "r"((a)[0]), "r"((a)[1]), "r"((a)[2]), "r"((a)[3]),                  \
          "r"((b)[0]), "r"((b)[1]))

#define LDSM_X4(r, addr)                                                       \
    asm volatile("ldmatrix.sync.aligned.m8n8.x4.shared.b16 {%0,%1,%2,%3}, [%4];" \
                 : "=r"((r)[0]), "=r"((r)[1]), "=r"((r)[2]), "=r"((r)[3])      \
                 : "r"(addr))

#define LDSM_X2(r, addr)                                                       \
    asm volatile("ldmatrix.sync.aligned.m8n8.x2.shared.b16 {%0,%1}, [%2];"     \
                 : "=r"((r)[0]), "=r"((r)[1]) : "r"(addr))

#define LDSM_X2T(r, addr)                                                      \
    asm volatile("ldmatrix.sync.aligned.m8n8.x2.trans.shared.b16 {%0,%1}, [%2];" \
                 : "=r"((r)[0]), "=r"((r)[1]) : "r"(addr))

#define CP_ASYNC16(dst, src)                                                   \
    asm volatile("cp.async.cg.shared.global [%0], [%1], 16;" ::"r"(dst), "l"(src))

// ---------------------------------------------------------------------------
// fp32 -> fp16 hi/lo split (elementwise)
// ---------------------------------------------------------------------------
__global__ void conv_split_kernel(const float* __restrict__ in,
                                  f16* __restrict__ h, f16* __restrict__ l,
                                  int n4)
{
    int i = blockIdx.x * blockDim.x + threadIdx.x;
    if (i < n4) {
        float4 v = ((const float4*)in)[i];
        f16 h0 = __float2half_rn(v.x), h1 = __float2half_rn(v.y);
        f16 h2 = __float2half_rn(v.z), h3 = __float2half_rn(v.w);
        f162 hh0 = {h0, h1}, hh1 = {h2, h3};
        ((f162*)h)[i * 2 + 0] = hh0;
        ((f162*)h)[i * 2 + 1] = hh1;
        f162 ll0 = {__float2half_rn(v.x - __half2float(h0)),
                    __float2half_rn(v.y - __half2float(h1))};
        f162 ll1 = {__float2half_rn(v.z - __half2float(h2)),
                    __float2half_rn(v.w - __half2float(h3))};
        ((f162*)l)[i * 2 + 0] = ll0;
        ((f162*)l)[i * 2 + 1] = ll1;
    }
}

// Transpose: fp32 [K][N] -> fp16 [N][K]
__global__ void convT_kernel(const float* __restrict__ in,
                             f16* __restrict__ h, int K, int N)
{
    __shared__ float t[32][33];
    int k0 = blockIdx.y * 32, n0 = blockIdx.x * 32;
    int tx = threadIdx.x, ty = threadIdx.y;
    #pragma unroll
    for (int i = 0; i < 4; ++i)
        t[ty + i * 8][tx] = in[(size_t)(k0 + ty + i * 8) * N + n0 + tx];
    __syncthreads();
    #pragma unroll
    for (int i = 0; i < 4; ++i) {
        float v = t[tx][ty + i * 8];
        int n = n0 + ty + i * 8;
        int k = k0 + tx;
        h[(size_t)n * K + k] = __float2half_rn(v);
    }
}

// ---------------------------------------------------------------------------
// Tensor-core GEMM (mma.sync fp16, fp32 acc), activation 2-term split:
// C = Ah*B + Al*B. Tile 128x128x32, 256 threads, smem stride 40.
// 3-stage cp.async pipeline, wait_group 1: loads for stage t have two full
// chunks to complete before use -> L2 latency fully hidden.
// ---------------------------------------------------------------------------
#define GS 40
#define STG_ELEMS (3 * 128 * GS)      // elems per stage (Ah,Al,B)
#define STG_BYTES (STG_ELEMS * 2)     // 30720
#define NSTAGE 3

template <int OUTF16>
__global__ __launch_bounds__(256, 2) void gemm_tc(
    const f16* __restrict__ Ah, const f16* __restrict__ Al,
    const f16* __restrict__ B,
    const float* __restrict__ bias,
    float* __restrict__ Cf, f16* __restrict__ Ch, f16* __restrict__ Cl,
    int M, int N, int K)
{
    extern __shared__ f16 sm[];

    const int tid = threadIdx.x;
    const int warp = tid >> 5, lane = tid & 31;
    const int bm = blockIdx.y * 128, bn = blockIdx.x * 128;
    const int wm = (warp >> 2) * 64, wn = (warp & 3) * 32;
    const int lrow = tid >> 1, lcol = (tid & 1) * 16;

    const f16* gsrc[3];
    gsrc[0] = Ah + (size_t)(bm + lrow) * K + lcol;
    gsrc[1] = Al + (size_t)(bm + lrow) * K + lcol;
    gsrc[2] = B + (size_t)(bn + lrow) * K + lcol;

    uint32_t sdst0[3];
    #pragma unroll
    for (int q = 0; q < 3; ++q)
        sdst0[q] = smem_u32(sm + q * 128 * GS + lrow * GS + lcol);

    const int nk = K >> 5;

    // issue loads for chunk t into stage t%3 (empty commit past the end --
    // keeps group accounting exact so wait_group 1 always means
    // "stage t complete" at iteration t)
    auto issue_loads = [&](int t) {
        if (t < nk) {
            uint32_t so = (uint32_t)(t % NSTAGE) * STG_BYTES;
            int off = t * 32;
            #pragma unroll
            for (int q = 0; q < 3; ++q) {
                CP_ASYNC16(sdst0[q] + so, gsrc[q] + off);
                CP_ASYNC16(sdst0[q] + so + 16, gsrc[q] + off + 8);
            }
        }
        asm volatile("cp.async.commit_group;");
    };

    float acc[4][4][4];
    #pragma unroll
    for (int i = 0; i < 4; ++i)
        #pragma unroll
        for (int j = 0; j < 4; ++j)
            #pragma unroll
            for (int r = 0; r < 4; ++r) acc[i][j][r] = 0.0f;

    // prologue: stages 0 and 1 in flight
    issue_loads(0);
    issue_loads(1);

    for (int t = 0; t < nk; ++t) {
        // groups g0..g(t+1) committed; leave newest pending -> g(t) (stage t) done
        asm volatile("cp.async.wait_group 1;");
        __syncthreads();   // cross-thread visibility of stage t; also write-
                           // after-read protection for the stage we now refill

        issue_loads(t + 2);   // overlaps with compute below

        const f16* base = sm + (t % NSTAGE) * STG_ELEMS;
        const f16* sAh = base;
        const f16* sAl = base + 128 * GS;
        const f16* sB  = base + 2 * 128 * GS;

        #pragma unroll
        for (int ks = 0; ks < 32; ks += 16) {
            uint32_t bh[4][2];
            #pragma unroll
            for (int nt = 0; nt < 4; ++nt) {
                uint32_t ab = smem_u32(&sB[(wn + nt * 8 + (lane & 7)) * GS +
                                           ks + ((lane >> 3) & 1) * 8]);
                LDSM_X2(bh[nt], ab);
            }
            #pragma unroll
            for (int mtp = 0; mtp < 4; mtp += 2) {
                uint32_t afh0[4], afl0[4], afh1[4], afl1[4];
                uint32_t a0 = smem_u32(&sAh[(wm + mtp * 16 + (lane & 15)) * GS +
                                            ks + (lane >> 4) * 8]);
                LDSM_X4(afh0, a0);
                uint32_t a1 = smem_u32(&sAl[(wm + mtp * 16 + (lane & 15)) * GS +
                                            ks + (lane >> 4) * 8]);
                LDSM_X4(afl0, a1);
                uint32_t a2 = smem_u32(&sAh[(wm + (mtp + 1) * 16 + (lane & 15)) * GS +
                                            ks + (lane >> 4) * 8]);
                LDSM_X4(afh1, a2);
                uint32_t a3 = smem_u32(&sAl[(wm + (mtp + 1) * 16 + (lane & 15)) * GS +
                                            ks + (lane >> 4) * 8]);
                LDSM_X4(afl1, a3);
                #pragma unroll
                for (int nt = 0; nt < 4; ++nt)
                    MMA_F16(acc[mtp][nt], afh0, bh[nt]);
                #pragma unroll
                for (int nt = 0; nt < 4; ++nt)
                    MMA_F16(acc[mtp + 1][nt], afh1, bh[nt]);
                #pragma unroll
                for (int nt = 0; nt < 4; ++nt)
                    MMA_F16(acc[mtp][nt], afl0, bh[nt]);
                #pragma unroll
                for (int nt = 0; nt < 4; ++nt)
                    MMA_F16(acc[mtp + 1][nt], afl1, bh[nt]);
            }
        }
    }

    #pragma unroll
    for (int mt = 0; mt < 4; ++mt) {
        #pragma unroll
        for (int nt = 0; nt < 4; ++nt) {
            int row = bm + wm + mt * 16 + (lane >> 2);
            int col = bn + wn + nt * 8 + (lane & 3) * 2;
            float bx = bias[col], by = bias[col + 1];
            float v0 = acc[mt][nt][0] + bx, v1 = acc[mt][nt][1] + by;
            float v2 = acc[mt][nt][2] + bx, v3 = acc[mt][nt][3] + by;
            if (OUTF16) {
                uint32_t hh0 = pack2h(v0, v1);
                f162 th0 = *(f162*)&hh0;
                *(uint32_t*)(Ch + (size_t)row * N + col) = hh0;
                *(uint32_t*)(Cl + (size_t)row * N + col) =
                    pack2h(v0 - __half2float(th0.x), v1 - __half2float(th0.y));
                uint32_t hh1 = pack2h(v2, v3);
                f162 th1 = *(f162*)&hh1;
                *(uint32_t*)(Ch + (size_t)(row + 8) * N + col) = hh1;
                *(uint32_t*)(Cl + (size_t)(row + 8) * N + col) =
                    pack2h(v2 - __half2float(th1.x), v3 - __half2float(th1.y));
            } else {
                float2 f0 = {v0, v1}, f1 = {v2, v3};
                *(float2*)(Cf + (size_t)row * N + col) = f0;
                *(float2*)(Cf + (size_t)(row + 8) * N + col) = f1;
            }
        }
    }
}

// ---------------------------------------------------------------------------
// Tensor-core sliding-window attention (mma.sync fp16, 3-product split).
// ---------------------------------------------------------------------------
#define A_KH 0
#define A_KL (128 * 72)
#define A_VH (2 * 128 * 72)
#define A_VL (3 * 128 * 72)
#define A_QH (4 * 128 * 72)
#define A_QL (4 * 128 * 72 + 64 * 72)
#define A_SMEM_ELEMS (4 * 128 * 72 + 2 * 64 * 72)   // 46080 elems = 92160 B

__global__ __launch_bounds__(128) void attn_tc_kernel(
    const f16* __restrict__ qkvh, const f16* __restrict__ qkvl,
    f16* __restrict__ outh, f16* __restrict__ outl)
{
    extern __shared__ f16 sm[];

    const int tid = threadIdx.x;
    const int warp = tid >> 5, lane = tid & 31;
    const int s0 = blockIdx.x * 64;
    const int h = blockIdx.y;
    const int b = blockIdx.z;

    {
        int pos = s0 - 32 + tid;
        uint4* dkh = (uint4*)(sm + A_KH + tid * 72);
        uint4* dkl = (uint4*)(sm + A_KL + tid * 72);
        uint4* dvh = (uint4*)(sm + A_VH + tid * 72);
        uint4* dvl = (uint4*)(sm + A_VL + tid * 72);
        if (pos >= 0 && pos < SEQ) {
            size_t rowb = (size_t)(b * SEQ + pos) * (3 * DMODEL);
            const uint4* kh = (const uint4*)(qkvh + rowb + DMODEL + h * HDIM);
            const uint4* kl = (const uint4*)(qkvl + rowb + DMODEL + h * HDIM);
            const uint4* vh = (const uint4*)(qkvh + rowb + 2 * DMODEL + h * HDIM);
            const uint4* vl = (const uint4*)(qkvl + rowb + 2 * DMODEL + h * HDIM);
            #pragma unroll
            for (int i = 0; i < 8; ++i) {
                dkh[i] = kh[i]; dkl[i] = kl[i];
                dvh[i] = vh[i]; dvl[i] = vl[i];
            }
        } else {
            uint4 z = {0, 0, 0, 0};
            #pragma unroll
            for (int i = 0; i < 8; ++i) {
                dkh[i] = z; dkl[i] = z; dvh[i] = z; dvl[i] = z;
            }
        }
        int qr = tid >> 1, qo = (tid & 1) * 32;
        size_t rq = (size_t)(b * SEQ + s0 + qr) * (3 * DMODEL) + h * HDIM + qo;
        const uint4* qh = (const uint4*)(qkvh + rq);
        const uint4* ql = (const uint4*)(qkvl + rq);
        uint4* dqh = (uint4*)(sm + A_QH + qr * 72 + qo);
        uint4* dql = (uint4*)(sm + A_QL + qr * 72 + qo);
        #pragma unroll
        for (int i = 0; i < 4; ++i) { dqh[i] = qh[i]; dql[i] = ql[i]; }
    }
    __syncthreads();

    // ---- S = Q K^T ----
    float s[16][4];
    #pragma unroll
    for (int nt = 0; nt < 16; ++nt)
        #pragma unroll
        for (int j = 0; j < 4; ++j) s[nt][j] = 0.0f;

    const int qrow = warp * 16 + (lane & 15);
    #pragma unroll
    for (int kk = 0; kk < 4; ++kk) {
        uint32_t ah[4], al[4];
        uint32_t aa = smem_u32(sm + A_QH + qrow * 72 + kk * 16 + (lane >> 4) * 8);
        LDSM_X4(ah, aa);
        uint32_t aa2 = smem_u32(sm + A_QL + qrow * 72 + kk * 16 + (lane >> 4) * 8);
        LDSM_X4(al, aa2);
        #pragma unroll
        for (int nt = 0; nt < 16; ++nt) {
            uint32_t bh[2], bl[2];
            uint32_t ba = smem_u32(sm + A_KH + (nt * 8 + (lane & 7)) * 72 +
                                   kk * 16 + ((lane >> 3) & 1) * 8);
            LDSM_X2(bh, ba);
            uint32_t ba2 = smem_u32(sm + A_KL + (nt * 8 + (lane & 7)) * 72 +
                                    kk * 16 + ((lane >> 3) & 1) * 8);
            LDSM_X2(bl, ba2);
            MMA_F16(s[nt], ah, bh);
            MMA_F16(s[nt], ah, bl);
            MMA_F16(s[nt], al, bh);
        }
    }

    // ---- scale + mask + softmax ----
    const int m0 = warp * 16 + (lane >> 2);
    const int m1 = m0 + 8;
    float mx0 = -1e30f, mx1 = -1e30f;
    #pragma unroll
    for (int nt = 0; nt < 16; ++nt) {
        #pragma unroll
        for (int jj = 0; jj < 2; ++jj) {
            int nn = nt * 8 + (lane & 3) * 2 + jj;
            int gpos = s0 - 32 + nn;
            bool vp = (gpos >= 0) && (gpos < SEQ);
            int d0 = nn - m0;
            s[nt][jj] = (vp && d0 >= 0 && d0 <= 64) ? s[nt][jj] * 0.125f : -1e9f;
            int d1 = nn - m1;
            s[nt][2 + jj] = (vp && d1 >= 0 && d1 <= 64) ? s[nt][2 + jj] * 0.125f : -1e9f;
        }
        mx0 = fmaxf(mx0, fmaxf(s[nt][0], s[nt][1]));
        mx1 = fmaxf(mx1, fmaxf(s[nt][2], s[nt][3]));
    }
    mx0 = fmaxf(mx0, __shfl_xor_sync(0xffffffffu, mx0, 1));
    mx0 = fmaxf(mx0, __shfl_xor_sync(0xffffffffu, mx0, 2));
    mx1 = fmaxf(mx1, __shfl_xor_sync(0xffffffffu, mx1, 1));
    mx1 = fmaxf(mx1, __shfl_xor_sync(0xffffffffu, mx1, 2));

    float sum0 = 0.f, sum1 = 0.f;
    #pragma unroll
    for (int nt = 0; nt < 16; ++nt) {
        s[nt][0] = __expf(s[nt][0] - mx0); sum0 += s[nt][0];
        s[nt][1] = __expf(s[nt][1] - mx0); sum0 += s[nt][1];
        s[nt][2] = __expf(s[nt][2] - mx1); sum1 += s[nt][2];
        s[nt][3] = __expf(s[nt][3] - mx1); sum1 += s[nt][3];
    }
    sum0 += __shfl_xor_sync(0xffffffffu, sum0, 1);
    sum0 += __shfl_xor_sync(0xffffffffu, sum0, 2);
    sum1 += __shfl_xor_sync(0xffffffffu, sum1, 1);
    sum1 += __shfl_xor_sync(0xffffffffu, sum1, 2);
    float inv0 = 1.0f / sum0, inv1 = 1.0f / sum1;

    // ---- O = P V ----
    float o[8][4];
    #pragma unroll
    for (int nt = 0; nt < 8; ++nt)
        #pragma unroll
        for (int j = 0; j < 4; ++j) o[nt][j] = 0.0f;

    #pragma unroll
    for (int kt = 0; kt < 8; ++kt) {
        float* pa = s[2 * kt];
        float* pb = s[2 * kt + 1];
        uint32_t ah[4], al[4];
        ah[0] = pack2h(pa[0], pa[1]);
        ah[1] = pack2h(pa[2], pa[3]);
        ah[2] = pack2h(pb[0], pb[1]);
        ah[3] = pack2h(pb[2], pb[3]);
        {
            f162 t0 = *(f162*)&ah[0], t1 = *(f162*)&ah[1];
            f162 t2 = *(f162*)&ah[2], t3 = *(f162*)&ah[3];
            al[0] = pack2h(pa[0] - __half2float(t0.x), pa[1] - __half2float(t0.y));
            al[1] = pack2h(pa[2] - __half2float(t1.x), pa[3] - __half2float(t1.y));
            al[2] = pack2h(pb[0] - __half2float(t2.x), pb[1] - __half2float(t2.y));
            al[3] = pack2h(pb[2] - __half2float(t3.x), pb[3] - __half2float(t3.y));
        }
        uint32_t vrow = (uint32_t)(kt * 16 + (lane & 15)) * 72;
        #pragma unroll
        for (int nt2 = 0; nt2 < 8; ++nt2) {
            uint32_t bh[2], bl[2];
            uint32_t ba = smem_u32(sm + A_VH + vrow + nt2 * 8);
            LDSM_X2T(bh, ba);
            uint32_t ba2 = smem_u32(sm + A_VL + vrow + nt2 * 8);
            LDSM_X2T(bl, ba2);
            MMA_F16(o[nt2], ah, bh);
            MMA_F16(o[nt2], ah, bl);
            MMA_F16(o[nt2], al, bh);
        }
    }

    // ---- normalize + emit fp16 hi/lo ----
    size_t r0 = (size_t)(b * SEQ + s0 + m0) * DMODEL + h * HDIM;
    size_t r1 = r0 + (size_t)8 * DMODEL;
    #pragma unroll
    for (int nt2 = 0; nt2 < 8; ++nt2) {
        int d = nt2 * 8 + (lane & 3) * 2;
        float v0 = o[nt2][0] * inv0, v1 = o[nt2][1] * inv0;
        float v2 = o[nt2][2] * inv1, v3 = o[nt2][3] * inv1;
        uint32_t hh0 = pack2h(v0, v1);
        f162 th0 = *(f162*)&hh0;
        *(uint32_t*)(outh + r0 + d) = hh0;
        *(uint32_t*)(outl + r0 + d) =
            pack2h(v0 - __half2float(th0.x), v1 - __half2float(th0.y));
        uint32_t hh1 = pack2h(v2, v3);
        f162 th1 = *(f162*)&hh1;
        *(uint32_t*)(outh + r1 + d) = hh1;
        *(uint32_t*)(outl + r1 + d) =
            pack2h(v2 - __half2float(th1.x), v3 - __half2float(th1.y));
    }
}

// ---------------------------------------------------------------------------
// Launch
// ---------------------------------------------------------------------------
extern "C" void kernel_launch(void* const* d_in, const int* in_sizes, int n_in,
                              void* d_out, int out_size)
{
    const float* x     = (const float*)d_in[0];
    const float* w_qkv = (const float*)d_in[1];
    const float* b_qkv = (const float*)d_in[2];
    const float* w_out = (const float*)d_in[3];
    const float* b_out = (const float*)d_in[4];
    float* out         = (float*)d_out;

    f16 *xh, *xl, *w1, *w2, *qh, *ql, *ah, *al;
    cudaGetSymbolAddress((void**)&xh, g_xh);
    cudaGetSymbolAddress((void**)&xl, g_xl);
    cudaGetSymbolAddress((void**)&w1, g_w1);
    cudaGetSymbolAddress((void**)&w2, g_w2);
    cudaGetSymbolAddress((void**)&qh, g_qkvh);
    cudaGetSymbolAddress((void**)&ql, g_qkvl);
    cudaGetSymbolAddress((void**)&ah, g_ah);
    cudaGetSymbolAddress((void**)&al, g_al);

    const int M = MROWS;

    {
        int n4 = (M * DMODEL) / 4;
        conv_split_kernel<<<(n4 + 255) / 256, 256>>>(x, xh, xl, n4);
    }
    {
        dim3 blk(32, 8);
        convT_kernel<<<dim3((3 * DMODEL) / 32, DMODEL / 32), blk>>>(
            w_qkv, w1, DMODEL, 3 * DMODEL);
        convT_kernel<<<dim3(DMODEL / 32, DMODEL / 32), blk>>>(
            w_out, w2, DMODEL, DMODEL);
    }

    const int gemm_smem = NSTAGE * STG_BYTES;   // 92160
    cudaFuncSetAttribute(gemm_tc<1>, cudaFuncAttributeMaxDynamicSharedMemorySize, gemm_smem);
    cudaFuncSetAttribute(gemm_tc<0>, cudaFuncAttributeMaxDynamicSharedMemorySize, gemm_smem);

    // GEMM1: qkv (fp16 hi/lo) = x @ w_qkv + b_qkv
    {
        dim3 grid((3 * DMODEL) / 128, M / 128);
        gemm_tc<1><<<grid, 256, gemm_smem>>>(xh, xl, w1, b_qkv,
                                             nullptr, qh, ql, M, 3 * DMODEL, DMODEL);
    }

    // attention (mma.sync fp16)
    {
        int smem = A_SMEM_ELEMS * (int)sizeof(f16);   // 92160
        cudaFuncSetAttribute(attn_tc_kernel,
                             cudaFuncAttributeMaxDynamicSharedMemorySize, smem);
        dim3 grid(SEQ / 64, NHEAD, BATCH);
        attn_tc_kernel<<<grid, 128, smem>>>(qh, ql, ah, al);
    }

    // GEMM2: out (fp32) = attn @ w_out + b_out
    {
        dim3 grid(DMODEL / 128, M / 128);
        gemm_tc<0><<<grid, 256, gemm_smem>>>(ah, al, w2, b_out,
                                             out, nullptr, nullptr, M, DMODEL, DMODEL);
    }
}